// round 1
// baseline (speedup 1.0000x reference)
#include <cuda_runtime.h>

// Problem constants
#define BB    16
#define CIN   128
#define COUT  128
#define HH    128
#define WW    128
#define KK    9        // 3x3 taps
#define SDIM  512

// Conv tiling
#define TH    4        // output rows per block
#define TW    32       // output cols per block
#define OCT   32       // output channels per block
#define CIT   16       // cin chunk staged in smem
#define ROWW  35       // smem input row pitch (34 used) -> bank-conflict-free

// Scratch (allocation-free rule: __device__ globals)
__device__ float g_s[BB * CIN];                       // [b][i]
__device__ float g_wmod[(size_t)BB * CIN * KK * COUT]; // [b][i][t][o]  (transposed for coalesced conv loads)

// ---------------------------------------------------------------------------
// Kernel 1: s[b][i] = lin_scale * (style[b] . mod_w[i]) + mod_b[i]
// ---------------------------------------------------------------------------
__global__ void modulate_kernel(const float* __restrict__ style,
                                const float* __restrict__ mod_w,
                                const float* __restrict__ mod_b) {
    const int b = blockIdx.x;
    const int i = threadIdx.x;
    const float lin_scale = 0.044194173824159216f;  // 1/sqrt(512)
    const float* st = style + b * SDIM;
    const float* mw = mod_w + i * SDIM;
    float acc = 0.f;
#pragma unroll 8
    for (int d = 0; d < SDIM; d++) acc += st[d] * mw[d];
    g_s[b * CIN + i] = acc * lin_scale + mod_b[i];
}

// ---------------------------------------------------------------------------
// Kernel 2: per (b, o): demod = rsqrt(sum_{i,t} (scale*w*s)^2 + 1e-8)
//           write g_wmod[b][i][t][o] = scale * w[o][i][t] * s[b][i] * demod
// ---------------------------------------------------------------------------
__global__ void weight_kernel(const float* __restrict__ weight) {
    const int o = blockIdx.x;
    const int b = blockIdx.y;
    const int i = threadIdx.x;  // 128 threads
    const float scale = 0.029462782549439483f;  // 1/sqrt(1152)

    const float s = g_s[b * CIN + i];
    float wm[KK];
    float sq = 0.f;
#pragma unroll
    for (int t = 0; t < KK; t++) {
        float w = weight[(o * CIN + i) * KK + t] * scale * s;
        wm[t] = w;
        sq += w * w;
    }
    // block reduce over 128 threads
    __shared__ float red[4];
#pragma unroll
    for (int off = 16; off > 0; off >>= 1)
        sq += __shfl_xor_sync(0xffffffffu, sq, off);
    if ((i & 31) == 0) red[i >> 5] = sq;
    __syncthreads();
    const float demod = rsqrtf(red[0] + red[1] + red[2] + red[3] + 1e-8f);

    float* dst = g_wmod + ((size_t)(b * CIN + i) * KK) * COUT + o;
#pragma unroll
    for (int t = 0; t < KK; t++)
        dst[t * COUT] = wm[t] * demod;
}

// ---------------------------------------------------------------------------
// Kernel 3: direct conv. Block: OCT=32 channels x (TH=4 x TW=32) pixels.
// 256 threads; thread owns 4 oc x 4 px. cin staged in chunks of CIT=16.
// ---------------------------------------------------------------------------
__global__ void __launch_bounds__(256, 4) conv_kernel(
    const float* __restrict__ x, float* __restrict__ out) {
    __shared__ float sIn[CIT][TH + 2][ROWW];
    __shared__ __align__(16) float sW[CIT][KK][OCT];

    const int b   = blockIdx.z;
    const int oc0 = blockIdx.y * OCT;
    const int sx  = blockIdx.x & 3;    // WW/TW = 4
    const int sy  = blockIdx.x >> 2;   // HH/TH = 32
    const int y0  = sy * TH;
    const int x0  = sx * TW;

    const int t  = threadIdx.x;
    const int pg = t & 31;             // pixel group
    const int cg = t >> 5;             // channel group 0..7 (4 oc each)
    const int pr = pg >> 3;            // row 0..3
    const int pc = (pg & 7) << 2;      // col 0,4,...,28

    float acc[4][4];
#pragma unroll
    for (int a = 0; a < 4; a++)
#pragma unroll
        for (int j = 0; j < 4; j++) acc[a][j] = 0.f;

    const float* xb = x + (size_t)b * CIN * HH * WW;

    for (int ci0 = 0; ci0 < CIN; ci0 += CIT) {
        __syncthreads();  // protect smem from previous chunk's readers
        // ---- stage input tile (CIT x 6 x 34, zero-padded halo) ----
        for (int e = t; e < CIT * (TH + 2) * 34; e += 256) {
            int ci  = e / ((TH + 2) * 34);
            int rem = e % ((TH + 2) * 34);
            int r   = rem / 34;
            int c   = rem % 34;
            int gy  = y0 + r - 1;
            int gx  = x0 + c - 1;
            float v = 0.f;
            if (gy >= 0 && gy < HH && gx >= 0 && gx < WW)
                v = xb[(size_t)(ci0 + ci) * HH * WW + gy * WW + gx];
            sIn[ci][r][c] = v;
        }
        // ---- stage weights (CIT x 9 x 32), coalesced over oc ----
        const float* wb = g_wmod + ((size_t)(b * CIN + ci0) * KK) * COUT + oc0;
        for (int e = t; e < CIT * KK * OCT; e += 256) {
            int ci  = e / (KK * OCT);
            int rem = e % (KK * OCT);
            int tap = rem >> 5;
            int oc  = rem & 31;
            sW[ci][tap][oc] = wb[(size_t)ci * KK * COUT + tap * COUT + oc];
        }
        __syncthreads();

#pragma unroll 1
        for (int ci = 0; ci < CIT; ci++) {
            float xin[3][6];
#pragma unroll
            for (int r = 0; r < 3; r++)
#pragma unroll
                for (int c = 0; c < 6; c++)
                    xin[r][c] = sIn[ci][pr + r][pc + c];
#pragma unroll
            for (int ky = 0; ky < 3; ky++)
#pragma unroll
                for (int kx = 0; kx < 3; kx++) {
                    float4 wv = *(const float4*)&sW[ci][ky * 3 + kx][cg * 4];
#pragma unroll
                    for (int j = 0; j < 4; j++) {
                        float xv = xin[ky][kx + j];
                        acc[0][j] += wv.x * xv;
                        acc[1][j] += wv.y * xv;
                        acc[2][j] += wv.z * xv;
                        acc[3][j] += wv.w * xv;
                    }
                }
        }
    }

    // ---- store: float4 along x ----
    float* ob = out + (((size_t)(b * COUT + oc0 + cg * 4) * HH) + y0 + pr) * WW + x0 + pc;
#pragma unroll
    for (int a = 0; a < 4; a++) {
        float4 v = make_float4(acc[a][0], acc[a][1], acc[a][2], acc[a][3]);
        *(float4*)(ob + (size_t)a * HH * WW) = v;
    }
}

// ---------------------------------------------------------------------------
extern "C" void kernel_launch(void* const* d_in, const int* in_sizes, int n_in,
                              void* d_out, int out_size) {
    const float* x      = (const float*)d_in[0];
    const float* style  = (const float*)d_in[1];
    const float* weight = (const float*)d_in[2];
    const float* mod_w  = (const float*)d_in[3];
    const float* mod_b  = (const float*)d_in[4];
    float* out = (float*)d_out;

    modulate_kernel<<<BB, CIN>>>(style, mod_w, mod_b);
    weight_kernel<<<dim3(COUT, BB), CIN>>>(weight);
    conv_kernel<<<dim3((HH / TH) * (WW / TW), COUT / OCT, BB), 256>>>(x, out);
}

// round 2
// speedup vs baseline: 1.0187x; 1.0187x over previous
#include <cuda_runtime.h>

// Problem constants
#define BB    16
#define CIN   128
#define COUT  128
#define HH    128
#define WW    128
#define KK    9        // 3x3 taps
#define SDIM  512

// Conv tiling
#define TH    4        // output rows per block
#define TW    32       // output cols per block
#define OCT   32       // output channels per block
#define CIT   16       // cin chunk staged in smem
#define ROWW  36       // smem input row pitch (34 used); mult of 4 -> aligned float4,
                       // and per-128-bit-phase (one pr row) covers all 32 banks conflict-free

// Scratch (allocation-free rule: __device__ globals)
__device__ float g_s[BB * CIN];                        // [b][i]
__device__ float g_wmod[(size_t)BB * CIN * KK * COUT]; // [b][i][t][o]

// ---- packed fp32x2 helpers (sm_100+ FFMA2 path; ptxas never auto-emits) ----
__device__ __forceinline__ unsigned long long pk2(float a, float b) {
    unsigned long long r;
    asm("mov.b64 %0, {%1, %2};" : "=l"(r) : "f"(a), "f"(b));
    return r;
}
__device__ __forceinline__ void ffma2(unsigned long long& d,
                                      unsigned long long a,
                                      unsigned long long b) {
    asm("fma.rn.f32x2 %0, %1, %2, %0;" : "+l"(d) : "l"(a), "l"(b));
}
__device__ __forceinline__ float2 upk2(unsigned long long v) {
    float2 f;
    asm("mov.b64 {%0, %1}, %2;" : "=f"(f.x), "=f"(f.y) : "l"(v));
    return f;
}

// ---------------------------------------------------------------------------
// Kernel 1: s[b][i] = lin_scale * (style[b] . mod_w[i]) + mod_b[i]
// Warp-per-output: 2048 warps total (was 2048 threads serial -> 40us latency).
// ---------------------------------------------------------------------------
__global__ void modulate_kernel(const float* __restrict__ style,
                                const float* __restrict__ mod_w,
                                const float* __restrict__ mod_b) {
    const int gw   = blockIdx.x * 8 + (threadIdx.x >> 5);  // global warp 0..2047
    const int lane = threadIdx.x & 31;
    const int b = gw >> 7;        // /CIN
    const int i = gw & 127;       // %CIN
    const float lin_scale = 0.044194173824159216f;  // 1/sqrt(512)
    const float* st = style + b * SDIM;
    const float* mw = mod_w + i * SDIM;
    float acc = 0.f;
#pragma unroll
    for (int d = 0; d < SDIM / 32; d++)
        acc += st[d * 32 + lane] * mw[d * 32 + lane];
#pragma unroll
    for (int off = 16; off > 0; off >>= 1)
        acc += __shfl_xor_sync(0xffffffffu, acc, off);
    if (lane == 0) g_s[b * CIN + i] = acc * lin_scale + mod_b[i];
}

// ---------------------------------------------------------------------------
// Kernel 2: per (b, o): demod = rsqrt(sum_{i,t} (scale*w*s)^2 + 1e-8)
//           write g_wmod[b][i][t][o] = scale * w[o][i][t] * s[b][i] * demod
// ---------------------------------------------------------------------------
__global__ void weight_kernel(const float* __restrict__ weight) {
    const int o = blockIdx.x;
    const int b = blockIdx.y;
    const int i = threadIdx.x;  // 128 threads
    const float scale = 0.029462782549439483f;  // 1/sqrt(1152)

    const float s = g_s[b * CIN + i];
    float wm[KK];
    float sq = 0.f;
#pragma unroll
    for (int t = 0; t < KK; t++) {
        float w = weight[(o * CIN + i) * KK + t] * scale * s;
        wm[t] = w;
        sq += w * w;
    }
    __shared__ float red[4];
#pragma unroll
    for (int off = 16; off > 0; off >>= 1)
        sq += __shfl_xor_sync(0xffffffffu, sq, off);
    if ((i & 31) == 0) red[i >> 5] = sq;
    __syncthreads();
    const float demod = rsqrtf(red[0] + red[1] + red[2] + red[3] + 1e-8f);

    float* dst = g_wmod + ((size_t)(b * CIN + i) * KK) * COUT + o;
#pragma unroll
    for (int t = 0; t < KK; t++)
        dst[t * COUT] = wm[t] * demod;
}

// ---------------------------------------------------------------------------
// Kernel 3: direct conv with packed FFMA2.
// Block: OCT=32 channels x (TH=4 x TW=32) pixels, 256 threads.
// Thread owns 4 oc (as 2 packed pairs) x 4 px.
// ---------------------------------------------------------------------------
__global__ void __launch_bounds__(256, 2) conv_kernel(
    const float* __restrict__ x, float* __restrict__ out) {
    __shared__ __align__(16) float sIn[CIT][TH + 2][ROWW];
    __shared__ __align__(16) float sW[CIT][KK][OCT];

    const int b   = blockIdx.z;
    const int oc0 = blockIdx.y * OCT;
    const int sx  = blockIdx.x & 3;    // WW/TW = 4
    const int sy  = blockIdx.x >> 2;   // HH/TH = 32
    const int y0  = sy * TH;
    const int x0  = sx * TW;

    const int t  = threadIdx.x;
    const int pg = t & 31;             // pixel group (lane)
    const int cg = t >> 5;             // channel group 0..7 (4 oc each)
    const int pr = pg >> 3;            // row 0..3
    const int pc = (pg & 7) << 2;      // col 0,4,...,28

    // acc pairs: accp[p][j] = {oc cg*4+2p, oc cg*4+2p+1} at pixel (pr, pc+j)
    unsigned long long accp[2][4];
#pragma unroll
    for (int p = 0; p < 2; p++)
#pragma unroll
        for (int j = 0; j < 4; j++) accp[p][j] = 0ull;

    const float* xb = x + (size_t)b * CIN * HH * WW;

    for (int ci0 = 0; ci0 < CIN; ci0 += CIT) {
        __syncthreads();
        // ---- stage input tile (CIT x 6 x 34, zero-padded halo) ----
        for (int e = t; e < CIT * (TH + 2) * 34; e += 256) {
            int ci  = e / ((TH + 2) * 34);
            int rem = e % ((TH + 2) * 34);
            int r   = rem / 34;
            int c   = rem % 34;
            int gy  = y0 + r - 1;
            int gx  = x0 + c - 1;
            float v = 0.f;
            if (gy >= 0 && gy < HH && gx >= 0 && gx < WW)
                v = xb[(size_t)(ci0 + ci) * HH * WW + gy * WW + gx];
            sIn[ci][r][c] = v;
        }
        // ---- stage weights (CIT x 9 x 32), coalesced over oc ----
        const float* wb = g_wmod + ((size_t)(b * CIN + ci0) * KK) * COUT + oc0;
        for (int e = t; e < CIT * KK * OCT; e += 256) {
            int ci  = e / (KK * OCT);
            int rem = e % (KK * OCT);
            int tap = rem >> 5;
            int oc  = rem & 31;
            sW[ci][tap][oc] = wb[(size_t)ci * KK * COUT + tap * COUT + oc];
        }
        __syncthreads();

#pragma unroll 1
        for (int ci = 0; ci < CIT; ci++) {
            // x registers: 3 rows x 6 cols (float4 + float2 per row)
            float xin[3][6];
#pragma unroll
            for (int r = 0; r < 3; r++) {
                const float* row = &sIn[ci][pr + r][pc];
                float4 a = *(const float4*)row;
                float2 c = *(const float2*)(row + 4);
                xin[r][0] = a.x; xin[r][1] = a.y; xin[r][2] = a.z; xin[r][3] = a.w;
                xin[r][4] = c.x; xin[r][5] = c.y;
            }
#pragma unroll
            for (int ky = 0; ky < 3; ky++)
#pragma unroll
                for (int kx = 0; kx < 3; kx++) {
                    // weight oc-pairs: one LDS.128 (warp-broadcast, conflict-free)
                    ulonglong2 wp = *(const ulonglong2*)&sW[ci][ky * 3 + kx][cg * 4];
#pragma unroll
                    for (int j = 0; j < 4; j++) {
                        float xv = xin[ky][kx + j];
                        unsigned long long xx = pk2(xv, xv);
                        ffma2(accp[0][j], wp.x, xx);
                        ffma2(accp[1][j], wp.y, xx);
                    }
                }
        }
    }

    // ---- store: unpack oc pairs, float4 along x per oc row ----
#pragma unroll
    for (int p = 0; p < 2; p++) {
        float2 u0 = upk2(accp[p][0]);
        float2 u1 = upk2(accp[p][1]);
        float2 u2 = upk2(accp[p][2]);
        float2 u3 = upk2(accp[p][3]);
        float* ob = out + (((size_t)(b * COUT + oc0 + cg * 4 + 2 * p) * HH) + y0 + pr) * WW + x0 + pc;
        *(float4*)ob = make_float4(u0.x, u1.x, u2.x, u3.x);
        *(float4*)(ob + (size_t)HH * WW) = make_float4(u0.y, u1.y, u2.y, u3.y);
    }
}

// ---------------------------------------------------------------------------
extern "C" void kernel_launch(void* const* d_in, const int* in_sizes, int n_in,
                              void* d_out, int out_size) {
    const float* x      = (const float*)d_in[0];
    const float* style  = (const float*)d_in[1];
    const float* weight = (const float*)d_in[2];
    const float* mod_w  = (const float*)d_in[3];
    const float* mod_b  = (const float*)d_in[4];
    float* out = (float*)d_out;

    modulate_kernel<<<BB * CIN / 8, 256>>>(style, mod_w, mod_b);
    weight_kernel<<<dim3(COUT, BB), CIN>>>(weight);
    conv_kernel<<<dim3((HH / TH) * (WW / TW), COUT / OCT, BB), 256>>>(x, out);
}